// round 1
// baseline (speedup 1.0000x reference)
#include <cuda_runtime.h>
#include <math.h>

#define BB 8
#define SS 8192
#define HH 768
#define NH 12
#define HD 64
#define NBN 4
#define RR 48
#define SCALEF 0.125f
#define NSPLIT 32

// Scratch (static device globals; no allocation)
__device__ float g_q[BB*NBN*HH];            //  24576
__device__ float g_qw[BB*RR*HH];            // 294912
__device__ float g_sc[BB*RR*SS];            // 3.15M floats (12.6 MB)
__device__ float g_part[BB*NSPLIT*RR*HH];   // 9.44M floats (37.7 MB)
__device__ float g_ctx[BB*RR*HH];

// ---------------------------------------------------------------------------
// Kernel 1a: q projection for first NBN tokens.  q[b,t,j] = x[b,t,:]·w_q[j,:]
// ---------------------------------------------------------------------------
__global__ void __launch_bounds__(256) k_qproj(const float* __restrict__ x,
                                               const float* __restrict__ wq) {
    int b = blockIdx.x >> 2, t = blockIdx.x & 3;
    __shared__ float sx[HH];
    const float* xr = x + (b * SS + t) * HH;
    for (int c = threadIdx.x; c < HH; c += 256) sx[c] = xr[c];
    __syncthreads();
    for (int j = threadIdx.x; j < HH; j += 256) {
        const float4* w = reinterpret_cast<const float4*>(wq + j * HH);
        const float4* s4 = reinterpret_cast<const float4*>(sx);
        float a = 0.f;
        #pragma unroll 4
        for (int c4 = 0; c4 < HH / 4; c4++) {
            float4 wv = w[c4], sv = s4[c4];
            a += wv.x * sv.x + wv.y * sv.y + wv.z * sv.z + wv.w * sv.w;
        }
        g_q[(b * NBN + t) * HH + j] = a;
    }
}

// ---------------------------------------------------------------------------
// Kernel 1b: fold K-projection into query.  qw[b,r,c] = SCALE * sum_d q·w_kv
//            r = h*4 + t
// ---------------------------------------------------------------------------
__global__ void __launch_bounds__(256) k_qw(const float* __restrict__ wkv) {
    int b = blockIdx.x / RR, r = blockIdx.x % RR;
    int h = r >> 2, t = r & 3;
    __shared__ float sq[HD];
    if (threadIdx.x < HD)
        sq[threadIdx.x] = g_q[(b * NBN + t) * HH + h * HD + threadIdx.x];
    __syncthreads();
    for (int c = threadIdx.x; c < HH; c += 256) {
        float a = 0.f;
        #pragma unroll 8
        for (int d = 0; d < HD; d++)
            a += sq[d] * wkv[(h * HD + d) * HH + c];
        g_qw[(b * RR + r) * HH + c] = a * SCALEF;
    }
}

// ---------------------------------------------------------------------------
// Kernel 2: scores[b,r,y] = qw[b,r,:] · x[b,y,:]
// Per-batch GEMM [48 x 768] x [768 x 8192].  CTA tile: 48 rows x 128 y.
// K-vectorized float4 accumulators; XOR-swizzled smem; reg-prefetch pipeline.
// ---------------------------------------------------------------------------
__global__ void __launch_bounds__(256) k_scores(const float* __restrict__ x) {
    const int b = blockIdx.y;
    const int y0 = blockIdx.x * 128;
    __shared__ float4 sX[128][8];   // [y][k4], chunk index XOR-swizzled by (y>>2)&7
    __shared__ float4 sQ[48][8];    // [r][k4]
    const int tid = threadIdx.x;
    const int i = tid & 31, j = tid >> 5;
    const float* xb = x + (b * SS + y0) * HH;
    const float* qb = g_qw + b * RR * HH;

    float4 acc[6][4];
    #pragma unroll
    for (int rr = 0; rr < 6; rr++)
        #pragma unroll
        for (int cc = 0; cc < 4; cc++) acc[rr][cc] = make_float4(0.f, 0.f, 0.f, 0.f);

    const int ly = tid >> 3, lq = tid & 7;   // x loads: rows ly+t*32, float4-chunk lq
    const int qr = tid >> 3, qq = tid & 7;   // qw loads
    float4 px[4], pq[2];

    auto LDG = [&](int c0) {
        #pragma unroll
        for (int t = 0; t < 4; t++)
            px[t] = *reinterpret_cast<const float4*>(xb + (ly + t * 32) * HH + c0 + lq * 4);
        pq[0] = *reinterpret_cast<const float4*>(qb + qr * HH + c0 + qq * 4);
        if (tid < 128)
            pq[1] = *reinterpret_cast<const float4*>(qb + (qr + 32) * HH + c0 + qq * 4);
    };
    auto STS = [&]() {
        #pragma unroll
        for (int t = 0; t < 4; t++) {
            int y = ly + t * 32;
            sX[y][lq ^ ((y >> 2) & 7)] = px[t];
        }
        sQ[qr][qq] = pq[0];
        if (tid < 128) sQ[qr + 32][qq] = pq[1];
    };
    auto COMP = [&]() {
        #pragma unroll
        for (int k4 = 0; k4 < 8; k4++) {
            float4 xv[4], qv[6];
            #pragma unroll
            for (int cc = 0; cc < 4; cc++)
                xv[cc] = sX[i * 4 + cc][k4 ^ (i & 7)];
            #pragma unroll
            for (int rr = 0; rr < 6; rr++)
                qv[rr] = sQ[j * 6 + rr][k4];
            #pragma unroll
            for (int rr = 0; rr < 6; rr++)
                #pragma unroll
                for (int cc = 0; cc < 4; cc++) {
                    acc[rr][cc].x += qv[rr].x * xv[cc].x;
                    acc[rr][cc].y += qv[rr].y * xv[cc].y;
                    acc[rr][cc].z += qv[rr].z * xv[cc].z;
                    acc[rr][cc].w += qv[rr].w * xv[cc].w;
                }
        }
    };

    LDG(0);
    STS();
    __syncthreads();
    for (int ch = 1; ch < 24; ch++) {
        LDG(ch * 32);
        COMP();
        __syncthreads();
        STS();
        __syncthreads();
    }
    COMP();

    float* outp = g_sc + (size_t)(b * RR) * SS + y0 + i * 4;
    #pragma unroll
    for (int rr = 0; rr < 6; rr++) {
        int r = j * 6 + rr;
        float4 o;
        o.x = acc[rr][0].x + acc[rr][0].y + acc[rr][0].z + acc[rr][0].w;
        o.y = acc[rr][1].x + acc[rr][1].y + acc[rr][1].z + acc[rr][1].w;
        o.z = acc[rr][2].x + acc[rr][2].y + acc[rr][2].z + acc[rr][2].w;
        o.w = acc[rr][3].x + acc[rr][3].y + acc[rr][3].z + acc[rr][3].w;
        *reinterpret_cast<float4*>(outp + (size_t)r * SS) = o;
    }
}

// ---------------------------------------------------------------------------
// Kernel 3: row softmax over S=8192, in place.  One CTA per (b,r) row.
// ---------------------------------------------------------------------------
__global__ void __launch_bounds__(256) k_softmax() {
    const int row = blockIdx.x;
    float* p = g_sc + (size_t)row * SS;
    __shared__ float sv[SS];
    __shared__ float red[8];

    float mx = -1e30f;
    for (int t = threadIdx.x; t < SS / 4; t += 256) {
        float4 v = reinterpret_cast<const float4*>(p)[t];
        reinterpret_cast<float4*>(sv)[t] = v;
        mx = fmaxf(mx, fmaxf(fmaxf(v.x, v.y), fmaxf(v.z, v.w)));
    }
    #pragma unroll
    for (int o = 16; o; o >>= 1) mx = fmaxf(mx, __shfl_xor_sync(0xffffffffu, mx, o));
    if ((threadIdx.x & 31) == 0) red[threadIdx.x >> 5] = mx;
    __syncthreads();
    float m = red[0];
    #pragma unroll
    for (int k = 1; k < 8; k++) m = fmaxf(m, red[k]);
    __syncthreads();

    float sum = 0.f;
    for (int t = threadIdx.x; t < SS / 4; t += 256) {
        float4 v = reinterpret_cast<float4*>(sv)[t];
        v.x = expf(v.x - m); v.y = expf(v.y - m);
        v.z = expf(v.z - m); v.w = expf(v.w - m);
        reinterpret_cast<float4*>(sv)[t] = v;
        sum += v.x + v.y + v.z + v.w;
    }
    #pragma unroll
    for (int o = 16; o; o >>= 1) sum += __shfl_xor_sync(0xffffffffu, sum, o);
    if ((threadIdx.x & 31) == 0) red[threadIdx.x >> 5] = sum;
    __syncthreads();
    float tot = 0.f;
    #pragma unroll
    for (int k = 0; k < 8; k++) tot += red[k];
    float inv = 1.0f / tot;

    for (int t = threadIdx.x; t < SS / 4; t += 256) {
        float4 v = reinterpret_cast<float4*>(sv)[t];
        v.x *= inv; v.y *= inv; v.z *= inv; v.w *= inv;
        reinterpret_cast<float4*>(p)[t] = v;
    }
}

// ---------------------------------------------------------------------------
// Kernel 4: ctx partials.  part[b,sp,r,c] = sum_{y in split} att[b,r,y]*x[b,y,c]
// CTA tile: 48 rows x 256 c, K(=y) range 256 per split.
// ---------------------------------------------------------------------------
__global__ void __launch_bounds__(256) k_ctx(const float* __restrict__ x) {
    const int ct = blockIdx.x;      // 0..2  (c tile of 256)
    const int sp = blockIdx.y;      // 0..31 (K split)
    const int b  = blockIdx.z;
    const int ybase = sp * 256;
    const int c0 = ct * 256;
    __shared__ float sXc[32][256];
    __shared__ float sA[48][32];
    const int tid = threadIdx.x, i = tid & 31, j = tid >> 5;

    float4 acc[6][2];
    #pragma unroll
    for (int rr = 0; rr < 6; rr++) {
        acc[rr][0] = make_float4(0.f, 0.f, 0.f, 0.f);
        acc[rr][1] = make_float4(0.f, 0.f, 0.f, 0.f);
    }

    const float* xb = x + (b * SS + ybase) * HH + c0;
    const float* ab = g_sc + (size_t)(b * RR) * SS + ybase;
    const int ly = tid >> 6, lc = tid & 63;   // x: rows ly+t*4, chunk lc
    const int ar = tid >> 3, aq = tid & 7;
    float4 px[8], pa[2];

    auto LDG = [&](int yc) {
        #pragma unroll
        for (int t = 0; t < 8; t++)
            px[t] = *reinterpret_cast<const float4*>(xb + (yc + ly + t * 4) * HH + lc * 4);
        pa[0] = *reinterpret_cast<const float4*>(ab + (size_t)ar * SS + yc + aq * 4);
        if (tid < 128)
            pa[1] = *reinterpret_cast<const float4*>(ab + (size_t)(ar + 32) * SS + yc + aq * 4);
    };
    auto STS = [&]() {
        #pragma unroll
        for (int t = 0; t < 8; t++)
            *reinterpret_cast<float4*>(&sXc[ly + t * 4][lc * 4]) = px[t];
        *reinterpret_cast<float4*>(&sA[ar][aq * 4]) = pa[0];
        if (tid < 128)
            *reinterpret_cast<float4*>(&sA[ar + 32][aq * 4]) = pa[1];
    };
    auto COMP = [&]() {
        #pragma unroll 8
        for (int kk = 0; kk < 32; kk++) {
            float4 xv0 = *reinterpret_cast<const float4*>(&sXc[kk][i * 4]);
            float4 xv1 = *reinterpret_cast<const float4*>(&sXc[kk][i * 4 + 128]);
            float a[6];
            #pragma unroll
            for (int rr = 0; rr < 6; rr++) a[rr] = sA[j * 6 + rr][kk];
            #pragma unroll
            for (int rr = 0; rr < 6; rr++) {
                acc[rr][0].x += a[rr] * xv0.x; acc[rr][0].y += a[rr] * xv0.y;
                acc[rr][0].z += a[rr] * xv0.z; acc[rr][0].w += a[rr] * xv0.w;
                acc[rr][1].x += a[rr] * xv1.x; acc[rr][1].y += a[rr] * xv1.y;
                acc[rr][1].z += a[rr] * xv1.z; acc[rr][1].w += a[rr] * xv1.w;
            }
        }
    };

    LDG(0);
    STS();
    __syncthreads();
    for (int ch = 1; ch < 8; ch++) {
        LDG(ch * 32);
        COMP();
        __syncthreads();
        STS();
        __syncthreads();
    }
    COMP();

    #pragma unroll
    for (int rr = 0; rr < 6; rr++) {
        int r = j * 6 + rr;
        float* pbase = g_part + (size_t)(((b * NSPLIT + sp) * RR) + r) * HH + c0;
        *reinterpret_cast<float4*>(pbase + i * 4) = acc[rr][0];
        *reinterpret_cast<float4*>(pbase + i * 4 + 128) = acc[rr][1];
    }
}

// ---------------------------------------------------------------------------
// Kernel 5: reduce split-K partials -> ctx
// ---------------------------------------------------------------------------
__global__ void __launch_bounds__(256) k_reduce() {
    int o = blockIdx.x * 256 + threadIdx.x;   // < B*R*H
    int b = o / (RR * HH);
    int rc = o - b * (RR * HH);
    const float* p = g_part + (size_t)b * NSPLIT * RR * HH + rc;
    float a = 0.f;
    #pragma unroll
    for (int s = 0; s < NSPLIT; s++) a += p[(size_t)s * RR * HH];
    g_ctx[o] = a;
}

// ---------------------------------------------------------------------------
// Kernel 6: epilogue.  o = ctx · W_v^T (per head), final = o @ w_out.T + b_out
// One CTA per (b, t).
// ---------------------------------------------------------------------------
__global__ void __launch_bounds__(256) k_out(const float* __restrict__ wkv,
                                             const float* __restrict__ wout,
                                             const float* __restrict__ bout,
                                             float* __restrict__ out) {
    int b = blockIdx.x >> 2, t = blockIdx.x & 3;
    __shared__ float sc_[NH][HH];   // 36 KB
    __shared__ float so[HH];        // 3 KB
    for (int idx = threadIdx.x; idx < NH * HH / 4; idx += 256) {
        int h = idx / (HH / 4), c4 = idx % (HH / 4);
        reinterpret_cast<float4*>(&sc_[h][0])[c4] =
            reinterpret_cast<const float4*>(g_ctx + (size_t)((b * RR) + h * NBN + t) * HH)[c4];
    }
    __syncthreads();
    for (int jj = threadIdx.x; jj < HH; jj += 256) {
        int h = jj >> 6;
        const float4* w = reinterpret_cast<const float4*>(wkv + (size_t)(HH + jj) * HH);
        const float4* cr = reinterpret_cast<const float4*>(&sc_[h][0]);
        float a = 0.f;
        #pragma unroll 4
        for (int c4 = 0; c4 < HH / 4; c4++) {
            float4 wv = w[c4], cv = cr[c4];
            a += wv.x * cv.x + wv.y * cv.y + wv.z * cv.z + wv.w * cv.w;
        }
        so[jj] = a;
    }
    __syncthreads();
    for (int jj = threadIdx.x; jj < HH; jj += 256) {
        const float4* w = reinterpret_cast<const float4*>(wout + (size_t)jj * HH);
        const float4* s4 = reinterpret_cast<const float4*>(so);
        float a = bout[jj];
        #pragma unroll 4
        for (int c4 = 0; c4 < HH / 4; c4++) {
            float4 wv = w[c4], sv = s4[c4];
            a += wv.x * sv.x + wv.y * sv.y + wv.z * sv.z + wv.w * sv.w;
        }
        out[(size_t)(b * NBN + t) * HH + jj] = a;
    }
}

// ---------------------------------------------------------------------------
extern "C" void kernel_launch(void* const* d_in, const int* in_sizes, int n_in,
                              void* d_out, int out_size) {
    const float* x    = (const float*)d_in[0];
    const float* wkv  = (const float*)d_in[1];
    const float* wq   = (const float*)d_in[2];
    const float* wout = (const float*)d_in[3];
    const float* bout = (const float*)d_in[4];
    float* out = (float*)d_out;

    k_qproj<<<BB * NBN, 256>>>(x, wq);
    k_qw<<<BB * RR, 256>>>(wkv);
    k_scores<<<dim3(SS / 128, BB), 256>>>(x);
    k_softmax<<<BB * RR, 256>>>();
    k_ctx<<<dim3(3, NSPLIT, BB), 256>>>(x);
    k_reduce<<<(BB * RR * HH) / 256, 256>>>();
    k_out<<<BB * NBN, 256>>>(wkv, wout, bout, out);
}

// round 2
// speedup vs baseline: 1.0025x; 1.0025x over previous
#include <cuda_runtime.h>
#include <math.h>

#define BB 8
#define SS 8192
#define HH 768
#define NH 12
#define HD 64
#define NBN 4
#define RR 48
#define SCALEF 0.125f
#define NSPLIT 32

// Scratch (static device globals; no allocation)
__device__ float g_q[BB*NBN*HH];            //  24576
__device__ float g_qw[BB*RR*HH];            // 294912
__device__ float g_sc[BB*RR*SS];            // 3.15M floats (12.6 MB)
__device__ float g_part[BB*NSPLIT*RR*HH];   // 9.44M floats (37.7 MB)
__device__ float g_ctx[BB*RR*HH];

// ---------------------------------------------------------------------------
// Kernel 1a: q projection for first NBN tokens.  q[b,t,j] = x[b,t,:]·w_q[j,:]
// ---------------------------------------------------------------------------
__global__ void __launch_bounds__(256) k_qproj(const float* __restrict__ x,
                                               const float* __restrict__ wq) {
    int b = blockIdx.x >> 2, t = blockIdx.x & 3;
    __shared__ float sx[HH];
    const float* xr = x + (b * SS + t) * HH;
    for (int c = threadIdx.x; c < HH; c += 256) sx[c] = xr[c];
    __syncthreads();
    for (int j = threadIdx.x; j < HH; j += 256) {
        const float4* w = reinterpret_cast<const float4*>(wq + j * HH);
        const float4* s4 = reinterpret_cast<const float4*>(sx);
        float a = 0.f;
        #pragma unroll 4
        for (int c4 = 0; c4 < HH / 4; c4++) {
            float4 wv = w[c4], sv = s4[c4];
            a += wv.x * sv.x + wv.y * sv.y + wv.z * sv.z + wv.w * sv.w;
        }
        g_q[(b * NBN + t) * HH + j] = a;
    }
}

// ---------------------------------------------------------------------------
// Kernel 1b: fold K-projection into query.  qw[b,r,c] = SCALE * sum_d q·w_kv
//            r = h*4 + t
// ---------------------------------------------------------------------------
__global__ void __launch_bounds__(256) k_qw(const float* __restrict__ wkv) {
    int b = blockIdx.x / RR, r = blockIdx.x % RR;
    int h = r >> 2, t = r & 3;
    __shared__ float sq[HD];
    if (threadIdx.x < HD)
        sq[threadIdx.x] = g_q[(b * NBN + t) * HH + h * HD + threadIdx.x];
    __syncthreads();
    for (int c = threadIdx.x; c < HH; c += 256) {
        float a = 0.f;
        #pragma unroll 8
        for (int d = 0; d < HD; d++)
            a += sq[d] * wkv[(h * HD + d) * HH + c];
        g_qw[(b * RR + r) * HH + c] = a * SCALEF;
    }
}

// ---------------------------------------------------------------------------
// Kernel 2: scores[b,r,y] = qw[b,r,:] · x[b,y,:]
// Per-batch GEMM [48 x 768] x [768 x 8192].  CTA tile: 48 rows x 128 y.
// K-vectorized float4 accumulators; XOR-swizzled smem; reg-prefetch pipeline.
// ---------------------------------------------------------------------------
__global__ void __launch_bounds__(256) k_scores(const float* __restrict__ x) {
    const int b = blockIdx.y;
    const int y0 = blockIdx.x * 128;
    __shared__ float4 sX[128][8];   // [y][k4], chunk index XOR-swizzled by (y>>2)&7
    __shared__ float4 sQ[48][8];    // [r][k4]
    const int tid = threadIdx.x;
    const int i = tid & 31, j = tid >> 5;
    const float* xb = x + (b * SS + y0) * HH;
    const float* qb = g_qw + b * RR * HH;

    float4 acc[6][4];
    #pragma unroll
    for (int rr = 0; rr < 6; rr++)
        #pragma unroll
        for (int cc = 0; cc < 4; cc++) acc[rr][cc] = make_float4(0.f, 0.f, 0.f, 0.f);

    const int ly = tid >> 3, lq = tid & 7;   // x loads: rows ly+t*32, float4-chunk lq
    const int qr = tid >> 3, qq = tid & 7;   // qw loads
    float4 px[4], pq[2];

    auto LDG = [&](int c0) {
        #pragma unroll
        for (int t = 0; t < 4; t++)
            px[t] = *reinterpret_cast<const float4*>(xb + (ly + t * 32) * HH + c0 + lq * 4);
        pq[0] = *reinterpret_cast<const float4*>(qb + qr * HH + c0 + qq * 4);
        if (tid < 128)
            pq[1] = *reinterpret_cast<const float4*>(qb + (qr + 32) * HH + c0 + qq * 4);
    };
    auto STS = [&]() {
        #pragma unroll
        for (int t = 0; t < 4; t++) {
            int y = ly + t * 32;
            sX[y][lq ^ ((y >> 2) & 7)] = px[t];
        }
        sQ[qr][qq] = pq[0];
        if (tid < 128) sQ[qr + 32][qq] = pq[1];
    };
    auto COMP = [&]() {
        #pragma unroll
        for (int k4 = 0; k4 < 8; k4++) {
            float4 xv[4], qv[6];
            #pragma unroll
            for (int cc = 0; cc < 4; cc++)
                xv[cc] = sX[i * 4 + cc][k4 ^ (i & 7)];
            #pragma unroll
            for (int rr = 0; rr < 6; rr++)
                qv[rr] = sQ[j * 6 + rr][k4];
            #pragma unroll
            for (int rr = 0; rr < 6; rr++)
                #pragma unroll
                for (int cc = 0; cc < 4; cc++) {
                    acc[rr][cc].x += qv[rr].x * xv[cc].x;
                    acc[rr][cc].y += qv[rr].y * xv[cc].y;
                    acc[rr][cc].z += qv[rr].z * xv[cc].z;
                    acc[rr][cc].w += qv[rr].w * xv[cc].w;
                }
        }
    };

    LDG(0);
    STS();
    __syncthreads();
    for (int ch = 1; ch < 24; ch++) {
        LDG(ch * 32);
        COMP();
        __syncthreads();
        STS();
        __syncthreads();
    }
    COMP();

    float* outp = g_sc + (size_t)(b * RR) * SS + y0 + i * 4;
    #pragma unroll
    for (int rr = 0; rr < 6; rr++) {
        int r = j * 6 + rr;
        float4 o;
        o.x = acc[rr][0].x + acc[rr][0].y + acc[rr][0].z + acc[rr][0].w;
        o.y = acc[rr][1].x + acc[rr][1].y + acc[rr][1].z + acc[rr][1].w;
        o.z = acc[rr][2].x + acc[rr][2].y + acc[rr][2].z + acc[rr][2].w;
        o.w = acc[rr][3].x + acc[rr][3].y + acc[rr][3].z + acc[rr][3].w;
        *reinterpret_cast<float4*>(outp + (size_t)r * SS) = o;
    }
}

// ---------------------------------------------------------------------------
// Kernel 3: row softmax over S=8192, in place.  One CTA per (b,r) row.
// ---------------------------------------------------------------------------
__global__ void __launch_bounds__(256) k_softmax() {
    const int row = blockIdx.x;
    float* p = g_sc + (size_t)row * SS;
    __shared__ float sv[SS];
    __shared__ float red[8];

    float mx = -1e30f;
    for (int t = threadIdx.x; t < SS / 4; t += 256) {
        float4 v = reinterpret_cast<const float4*>(p)[t];
        reinterpret_cast<float4*>(sv)[t] = v;
        mx = fmaxf(mx, fmaxf(fmaxf(v.x, v.y), fmaxf(v.z, v.w)));
    }
    #pragma unroll
    for (int o = 16; o; o >>= 1) mx = fmaxf(mx, __shfl_xor_sync(0xffffffffu, mx, o));
    if ((threadIdx.x & 31) == 0) red[threadIdx.x >> 5] = mx;
    __syncthreads();
    float m = red[0];
    #pragma unroll
    for (int k = 1; k < 8; k++) m = fmaxf(m, red[k]);
    __syncthreads();

    float sum = 0.f;
    for (int t = threadIdx.x; t < SS / 4; t += 256) {
        float4 v = reinterpret_cast<float4*>(sv)[t];
        v.x = expf(v.x - m); v.y = expf(v.y - m);
        v.z = expf(v.z - m); v.w = expf(v.w - m);
        reinterpret_cast<float4*>(sv)[t] = v;
        sum += v.x + v.y + v.z + v.w;
    }
    #pragma unroll
    for (int o = 16; o; o >>= 1) sum += __shfl_xor_sync(0xffffffffu, sum, o);
    if ((threadIdx.x & 31) == 0) red[threadIdx.x >> 5] = sum;
    __syncthreads();
    float tot = 0.f;
    #pragma unroll
    for (int k = 0; k < 8; k++) tot += red[k];
    float inv = 1.0f / tot;

    for (int t = threadIdx.x; t < SS / 4; t += 256) {
        float4 v = reinterpret_cast<float4*>(sv)[t];
        v.x *= inv; v.y *= inv; v.z *= inv; v.w *= inv;
        reinterpret_cast<float4*>(p)[t] = v;
    }
}

// ---------------------------------------------------------------------------
// Kernel 4: ctx partials.  part[b,sp,r,c] = sum_{y in split} att[b,r,y]*x[b,y,c]
// CTA tile: 48 rows x 256 c, K(=y) range 256 per split.
// ---------------------------------------------------------------------------
__global__ void __launch_bounds__(256) k_ctx(const float* __restrict__ x) {
    const int ct = blockIdx.x;      // 0..2  (c tile of 256)
    const int sp = blockIdx.y;      // 0..31 (K split)
    const int b  = blockIdx.z;
    const int ybase = sp * 256;
    const int c0 = ct * 256;
    __shared__ float sXc[32][256];
    __shared__ float sA[48][32];
    const int tid = threadIdx.x, i = tid & 31, j = tid >> 5;

    float4 acc[6][2];
    #pragma unroll
    for (int rr = 0; rr < 6; rr++) {
        acc[rr][0] = make_float4(0.f, 0.f, 0.f, 0.f);
        acc[rr][1] = make_float4(0.f, 0.f, 0.f, 0.f);
    }

    const float* xb = x + (b * SS + ybase) * HH + c0;
    const float* ab = g_sc + (size_t)(b * RR) * SS + ybase;
    const int ly = tid >> 6, lc = tid & 63;   // x: rows ly+t*4, chunk lc
    const int ar = tid >> 3, aq = tid & 7;
    float4 px[8], pa[2];

    auto LDG = [&](int yc) {
        #pragma unroll
        for (int t = 0; t < 8; t++)
            px[t] = *reinterpret_cast<const float4*>(xb + (yc + ly + t * 4) * HH + lc * 4);
        pa[0] = *reinterpret_cast<const float4*>(ab + (size_t)ar * SS + yc + aq * 4);
        if (tid < 128)
            pa[1] = *reinterpret_cast<const float4*>(ab + (size_t)(ar + 32) * SS + yc + aq * 4);
    };
    auto STS = [&]() {
        #pragma unroll
        for (int t = 0; t < 8; t++)
            *reinterpret_cast<float4*>(&sXc[ly + t * 4][lc * 4]) = px[t];
        *reinterpret_cast<float4*>(&sA[ar][aq * 4]) = pa[0];
        if (tid < 128)
            *reinterpret_cast<float4*>(&sA[ar + 32][aq * 4]) = pa[1];
    };
    auto COMP = [&]() {
        #pragma unroll 8
        for (int kk = 0; kk < 32; kk++) {
            float4 xv0 = *reinterpret_cast<const float4*>(&sXc[kk][i * 4]);
            float4 xv1 = *reinterpret_cast<const float4*>(&sXc[kk][i * 4 + 128]);
            float a[6];
            #pragma unroll
            for (int rr = 0; rr < 6; rr++) a[rr] = sA[j * 6 + rr][kk];
            #pragma unroll
            for (int rr = 0; rr < 6; rr++) {
                acc[rr][0].x += a[rr] * xv0.x; acc[rr][0].y += a[rr] * xv0.y;
                acc[rr][0].z += a[rr] * xv0.z; acc[rr][0].w += a[rr] * xv0.w;
                acc[rr][1].x += a[rr] * xv1.x; acc[rr][1].y += a[rr] * xv1.y;
                acc[rr][1].z += a[rr] * xv1.z; acc[rr][1].w += a[rr] * xv1.w;
            }
        }
    };

    LDG(0);
    STS();
    __syncthreads();
    for (int ch = 1; ch < 8; ch++) {
        LDG(ch * 32);
        COMP();
        __syncthreads();
        STS();
        __syncthreads();
    }
    COMP();

    #pragma unroll
    for (int rr = 0; rr < 6; rr++) {
        int r = j * 6 + rr;
        float* pbase = g_part + (size_t)(((b * NSPLIT + sp) * RR) + r) * HH + c0;
        *reinterpret_cast<float4*>(pbase + i * 4) = acc[rr][0];
        *reinterpret_cast<float4*>(pbase + i * 4 + 128) = acc[rr][1];
    }
}

// ---------------------------------------------------------------------------
// Kernel 5: reduce split-K partials -> ctx
// ---------------------------------------------------------------------------
__global__ void __launch_bounds__(256) k_reduce() {
    int o = blockIdx.x * 256 + threadIdx.x;   // < B*R*H
    int b = o / (RR * HH);
    int rc = o - b * (RR * HH);
    const float* p = g_part + (size_t)b * NSPLIT * RR * HH + rc;
    float a = 0.f;
    #pragma unroll
    for (int s = 0; s < NSPLIT; s++) a += p[(size_t)s * RR * HH];
    g_ctx[o] = a;
}

// ---------------------------------------------------------------------------
// Kernel 6: epilogue.  o = ctx · W_v^T (per head), final = o @ w_out.T + b_out
// One CTA per (b, t).
// ---------------------------------------------------------------------------
__global__ void __launch_bounds__(256) k_out(const float* __restrict__ wkv,
                                             const float* __restrict__ wout,
                                             const float* __restrict__ bout,
                                             float* __restrict__ out) {
    int b = blockIdx.x >> 2, t = blockIdx.x & 3;
    __shared__ float sc_[NH][HH];   // 36 KB
    __shared__ float so[HH];        // 3 KB
    for (int idx = threadIdx.x; idx < NH * HH / 4; idx += 256) {
        int h = idx / (HH / 4), c4 = idx % (HH / 4);
        reinterpret_cast<float4*>(&sc_[h][0])[c4] =
            reinterpret_cast<const float4*>(g_ctx + (size_t)((b * RR) + h * NBN + t) * HH)[c4];
    }
    __syncthreads();
    for (int jj = threadIdx.x; jj < HH; jj += 256) {
        int h = jj >> 6;
        const float4* w = reinterpret_cast<const float4*>(wkv + (size_t)(HH + jj) * HH);
        const float4* cr = reinterpret_cast<const float4*>(&sc_[h][0]);
        float a = 0.f;
        #pragma unroll 4
        for (int c4 = 0; c4 < HH / 4; c4++) {
            float4 wv = w[c4], cv = cr[c4];
            a += wv.x * cv.x + wv.y * cv.y + wv.z * cv.z + wv.w * cv.w;
        }
        so[jj] = a;
    }
    __syncthreads();
    for (int jj = threadIdx.x; jj < HH; jj += 256) {
        const float4* w = reinterpret_cast<const float4*>(wout + (size_t)jj * HH);
        const float4* s4 = reinterpret_cast<const float4*>(so);
        float a = bout[jj];
        #pragma unroll 4
        for (int c4 = 0; c4 < HH / 4; c4++) {
            float4 wv = w[c4], sv = s4[c4];
            a += wv.x * sv.x + wv.y * sv.y + wv.z * sv.z + wv.w * sv.w;
        }
        out[(size_t)(b * NBN + t) * HH + jj] = a;
    }
}

// ---------------------------------------------------------------------------
extern "C" void kernel_launch(void* const* d_in, const int* in_sizes, int n_in,
                              void* d_out, int out_size) {
    const float* x    = (const float*)d_in[0];
    const float* wkv  = (const float*)d_in[1];
    const float* wq   = (const float*)d_in[2];
    const float* wout = (const float*)d_in[3];
    const float* bout = (const float*)d_in[4];
    float* out = (float*)d_out;

    k_qproj<<<BB * NBN, 256>>>(x, wq);
    k_qw<<<BB * RR, 256>>>(wkv);
    k_scores<<<dim3(SS / 128, BB), 256>>>(x);
    k_softmax<<<BB * RR, 256>>>();
    k_ctx<<<dim3(3, NSPLIT, BB), 256>>>(x);
    k_reduce<<<(BB * RR * HH) / 256, 256>>>();
    k_out<<<BB * NBN, 256>>>(wkv, wout, bout, out);
}

// round 4
// speedup vs baseline: 1.2873x; 1.2841x over previous
#include <cuda_runtime.h>
#include <cuda_bf16.h>
#include <cstdint>
#include <math.h>

#define BB 8
#define SS 8192
#define HH 768
#define NH 12
#define HD 64
#define NBN 4
#define RR 48
#define SCALEF 0.125f
#define NSPLIT 8

// ---------------- global scratch ----------------
__device__ float g_q[BB*NBN*HH];
__device__ __nv_bfloat16 g_qwh[BB*RR*HH];
__device__ __nv_bfloat16 g_qwl[BB*RR*HH];
__device__ float g_sc[(size_t)BB*RR*SS];           // logits fp32
__device__ __nv_bfloat16 g_ath[(size_t)BB*RR*SS];  // att hi
__device__ __nv_bfloat16 g_atl[(size_t)BB*RR*SS];  // att lo
__device__ float g_part[(size_t)BB*NSPLIT*RR*HH];
__device__ float g_ctx[BB*RR*HH];

// ---------------- helpers ----------------
__device__ __forceinline__ uint32_t smem_u32(const void* p) {
    uint32_t a;
    asm("{ .reg .u64 t; cvta.to.shared.u64 t, %1; cvt.u32.u64 %0, t; }" : "=r"(a) : "l"(p));
    return a;
}
__device__ __forceinline__ void ldsm4(uint32_t* r, uint32_t a) {
    asm volatile("ldmatrix.sync.aligned.m8n8.x4.shared.b16 {%0,%1,%2,%3}, [%4];"
        : "=r"(r[0]), "=r"(r[1]), "=r"(r[2]), "=r"(r[3]) : "r"(a));
}
__device__ __forceinline__ void ldsm4t(uint32_t* r, uint32_t a) {
    asm volatile("ldmatrix.sync.aligned.m8n8.x4.trans.shared.b16 {%0,%1,%2,%3}, [%4];"
        : "=r"(r[0]), "=r"(r[1]), "=r"(r[2]), "=r"(r[3]) : "r"(a));
}
__device__ __forceinline__ void mma_bf16(float* c, const uint32_t* a, uint32_t b0, uint32_t b1) {
    asm volatile("mma.sync.aligned.m16n8k16.row.col.f32.bf16.bf16.f32 "
        "{%0,%1,%2,%3}, {%4,%5,%6,%7}, {%8,%9}, {%0,%1,%2,%3};"
        : "+f"(c[0]), "+f"(c[1]), "+f"(c[2]), "+f"(c[3])
        : "r"(a[0]), "r"(a[1]), "r"(a[2]), "r"(a[3]), "r"(b0), "r"(b1));
}
__device__ __forceinline__ uint32_t pk2(float a, float b) {
    __nv_bfloat162 t = __floats2bfloat162_rn(a, b);
    return *reinterpret_cast<uint32_t*>(&t);
}
__device__ __forceinline__ float rz(float v) {
    return v - __bfloat162float(__float2bfloat16_rn(v));
}

// =================== Kernel 1a: q projection ===================
__global__ void __launch_bounds__(256) k_qproj(const float* __restrict__ x,
                                               const float* __restrict__ wq) {
    int b = blockIdx.x >> 2, t = blockIdx.x & 3;
    __shared__ float sx[HH];
    const float* xr = x + ((size_t)b * SS + t) * HH;
    for (int c = threadIdx.x; c < HH; c += 256) sx[c] = xr[c];
    __syncthreads();
    for (int j = threadIdx.x; j < HH; j += 256) {
        const float4* w = reinterpret_cast<const float4*>(wq + (size_t)j * HH);
        const float4* s4 = reinterpret_cast<const float4*>(sx);
        float a = 0.f;
        #pragma unroll 4
        for (int c4 = 0; c4 < HH / 4; c4++) {
            float4 wv = w[c4], sv = s4[c4];
            a += wv.x * sv.x + wv.y * sv.y + wv.z * sv.z + wv.w * sv.w;
        }
        g_q[(b * NBN + t) * HH + j] = a;
    }
}

// ========== Kernel 1b: qw = SCALE*(q @ W_k), split to bf16 hi/lo ==========
__global__ void __launch_bounds__(256) k_qw(const float* __restrict__ wkv) {
    int b = blockIdx.x / RR, r = blockIdx.x % RR;
    int h = r >> 2, t = r & 3;
    __shared__ float sq[HD];
    if (threadIdx.x < HD)
        sq[threadIdx.x] = g_q[(b * NBN + t) * HH + h * HD + threadIdx.x];
    __syncthreads();
    for (int c = threadIdx.x; c < HH; c += 256) {
        float a = 0.f;
        #pragma unroll 8
        for (int d = 0; d < HD; d++)
            a += sq[d] * wkv[(size_t)(h * HD + d) * HH + c];
        a *= SCALEF;
        size_t idx = (size_t)(b * RR + r) * HH + c;
        __nv_bfloat16 hi = __float2bfloat16_rn(a);
        g_qwh[idx] = hi;
        g_qwl[idx] = __float2bfloat16_rn(a - __bfloat162float(hi));
    }
}

// =================== Kernel 2: scores via mma.sync bf16 split ===================
// Per CTA: D[y=128][r=48] over K=768 in 24 chunks of 32.
// 8 warps; warp w -> y rows w*16..w*16+15, all 48 r (6 n-tiles of 8).
#define SXP 40   // padded row stride (elems) for 32-k X tile
__global__ void __launch_bounds__(256) k_scores_mma(const float* __restrict__ x) {
    __shared__ __nv_bfloat16 sXh[128 * SXP];
    __shared__ __nv_bfloat16 sXl[128 * SXP];
    __shared__ __nv_bfloat16 sQh[48 * SXP];
    __shared__ __nv_bfloat16 sQl[48 * SXP];

    const int tid = threadIdx.x, w = tid >> 5, l = tid & 31;
    const int b = blockIdx.y;
    const int y0 = blockIdx.x * 128;

    const float* xb = x + ((size_t)b * SS + y0) * HH;
    const __nv_bfloat16* qh = g_qwh + (size_t)b * RR * HH;
    const __nv_bfloat16* ql = g_qwl + (size_t)b * RR * HH;

    float acc[6][4];
    #pragma unroll
    for (int n = 0; n < 6; n++)
        #pragma unroll
        for (int k = 0; k < 4; k++) acc[n][k] = 0.f;

    const uint32_t uXh = smem_u32(sXh), uXl = smem_u32(sXl);
    const uint32_t uQh = smem_u32(sQh), uQl = smem_u32(sQl);

    for (int ch = 0; ch < 24; ch++) {
        const int c0 = ch * 32;
        // ---- convert X chunk [128 y x 32 k] fp32 -> bf16 hi/lo ----
        #pragma unroll
        for (int t = tid, it = 0; it < 4; t += 256, it++) {
            int row = t >> 3, c4 = t & 7;
            float4 v = *reinterpret_cast<const float4*>(xb + (size_t)row * HH + c0 + c4 * 4);
            uint2 h = make_uint2(pk2(v.x, v.y), pk2(v.z, v.w));
            uint2 lo = make_uint2(pk2(rz(v.x), rz(v.y)), pk2(rz(v.z), rz(v.w)));
            *reinterpret_cast<uint2*>(&sXh[row * SXP + c4 * 4]) = h;
            *reinterpret_cast<uint2*>(&sXl[row * SXP + c4 * 4]) = lo;
        }
        // ---- copy Q chunk [48 r x 32 k] bf16 hi/lo ----
        if (tid < 192) {
            int row = tid >> 2, q = tid & 3;
            uint4 vh = *reinterpret_cast<const uint4*>(qh + (size_t)row * HH + c0 + q * 8);
            uint4 vl = *reinterpret_cast<const uint4*>(ql + (size_t)row * HH + c0 + q * 8);
            *reinterpret_cast<uint4*>(&sQh[row * SXP + q * 8]) = vh;
            *reinterpret_cast<uint4*>(&sQl[row * SXP + q * 8]) = vl;
        }
        __syncthreads();
        // ---- MMA: 2 k-steps of 16 ----
        #pragma unroll
        for (int ks = 0; ks < 2; ks++) {
            const int k0 = ks * 16;
            uint32_t arow = w * 16 + (l & 15);
            uint32_t acol = k0 + ((l >> 4) << 3);
            uint32_t aoff = (arow * SXP + acol) * 2;
            uint32_t ah[4], al[4];
            ldsm4(ah, uXh + aoff);
            ldsm4(al, uXl + aoff);
            #pragma unroll
            for (int ntp = 0; ntp < 3; ntp++) {
                uint32_t brow = ntp * 16 + ((l >> 4) << 3) + (l & 7);
                uint32_t bcol = k0 + (l & 8);
                uint32_t boff = (brow * SXP + bcol) * 2;
                uint32_t bh[4], bl[4];
                ldsm4(bh, uQh + boff);
                ldsm4(bl, uQl + boff);
                mma_bf16(acc[ntp * 2],     ah, bh[0], bh[1]);
                mma_bf16(acc[ntp * 2],     ah, bl[0], bl[1]);
                mma_bf16(acc[ntp * 2],     al, bh[0], bh[1]);
                mma_bf16(acc[ntp * 2 + 1], ah, bh[2], bh[3]);
                mma_bf16(acc[ntp * 2 + 1], ah, bl[2], bl[3]);
                mma_bf16(acc[ntp * 2 + 1], al, bh[2], bh[3]);
            }
        }
        __syncthreads();
    }

    // ---- epilogue: c0,c1 -> (y, r..r+1); c2,c3 -> (y+8, r..r+1) ----
    float* ob = g_sc + (size_t)b * RR * SS;
    int ybase = y0 + w * 16 + (l >> 2);
    #pragma unroll
    for (int nt = 0; nt < 6; nt++) {
        int r = nt * 8 + (l & 3) * 2;
        ob[(size_t)r * SS + ybase]           = acc[nt][0];
        ob[(size_t)(r + 1) * SS + ybase]     = acc[nt][1];
        ob[(size_t)r * SS + ybase + 8]       = acc[nt][2];
        ob[(size_t)(r + 1) * SS + ybase + 8] = acc[nt][3];
    }
}

// =================== Kernel 3: softmax -> bf16 hi/lo ===================
__global__ void __launch_bounds__(256) k_softmax() {
    const int row = blockIdx.x;
    const float* p = g_sc + (size_t)row * SS;
    __nv_bfloat16* oh = g_ath + (size_t)row * SS;
    __nv_bfloat16* ol = g_atl + (size_t)row * SS;
    __shared__ float sv[SS];
    __shared__ float red[8];

    float mx = -1e30f;
    for (int t = threadIdx.x; t < SS / 4; t += 256) {
        float4 v = reinterpret_cast<const float4*>(p)[t];
        reinterpret_cast<float4*>(sv)[t] = v;
        mx = fmaxf(mx, fmaxf(fmaxf(v.x, v.y), fmaxf(v.z, v.w)));
    }
    #pragma unroll
    for (int o = 16; o; o >>= 1) mx = fmaxf(mx, __shfl_xor_sync(0xffffffffu, mx, o));
    if ((threadIdx.x & 31) == 0) red[threadIdx.x >> 5] = mx;
    __syncthreads();
    float m = red[0];
    #pragma unroll
    for (int k = 1; k < 8; k++) m = fmaxf(m, red[k]);
    __syncthreads();

    float sum = 0.f;
    for (int t = threadIdx.x; t < SS / 4; t += 256) {
        float4 v = reinterpret_cast<float4*>(sv)[t];
        v.x = expf(v.x - m); v.y = expf(v.y - m);
        v.z = expf(v.z - m); v.w = expf(v.w - m);
        reinterpret_cast<float4*>(sv)[t] = v;
        sum += v.x + v.y + v.z + v.w;
    }
    #pragma unroll
    for (int o = 16; o; o >>= 1) sum += __shfl_xor_sync(0xffffffffu, sum, o);
    if ((threadIdx.x & 31) == 0) red[threadIdx.x >> 5] = sum;
    __syncthreads();
    float tot = 0.f;
    #pragma unroll
    for (int k = 0; k < 8; k++) tot += red[k];
    float inv = 1.0f / tot;

    for (int t = threadIdx.x; t < SS / 4; t += 256) {
        float4 v = reinterpret_cast<float4*>(sv)[t];
        v.x *= inv; v.y *= inv; v.z *= inv; v.w *= inv;
        reinterpret_cast<uint2*>(oh)[t] = make_uint2(pk2(v.x, v.y), pk2(v.z, v.w));
        reinterpret_cast<uint2*>(ol)[t] = make_uint2(pk2(rz(v.x), rz(v.y)), pk2(rz(v.z), rz(v.w)));
    }
}

// =================== Kernel 4: ctx via mma.sync (split-K) ===================
// Per CTA: D[r=48][c=64] for one (b, split, c-chunk); K(y) range 1024, chunks 64.
// 6 warps; warp w -> m-tile (w>>1)*16, c-half (w&1)*32 (4 n-tiles).
#define CXP 72   // padded row stride (elems) for 64-wide tiles
__global__ void __launch_bounds__(192) k_ctx_mma(const float* __restrict__ x) {
    __shared__ __nv_bfloat16 sAh[48 * CXP];
    __shared__ __nv_bfloat16 sAl[48 * CXP];
    __shared__ __nv_bfloat16 sXh[64 * CXP];
    __shared__ __nv_bfloat16 sXl[64 * CXP];

    const int tid = threadIdx.x, w = tid >> 5, l = tid & 31;
    const int ct = blockIdx.x;            // 0..11
    const int sp = blockIdx.y;            // 0..NSPLIT-1
    const int b  = blockIdx.z;
    const int c0 = ct * 64;
    const int ybase = sp * (SS / NSPLIT); // 1024

    const float* xb = x + (size_t)b * SS * HH + c0;
    const __nv_bfloat16* ah = g_ath + (size_t)b * RR * SS;
    const __nv_bfloat16* al = g_atl + (size_t)b * RR * SS;

    const int mt = w >> 1;                // 0..2
    const int cbase = (w & 1) * 32;

    float acc[4][4];
    #pragma unroll
    for (int n = 0; n < 4; n++)
        #pragma unroll
        for (int k = 0; k < 4; k++) acc[n][k] = 0.f;

    const uint32_t uAh = smem_u32(sAh), uAl = smem_u32(sAl);
    const uint32_t uXh = smem_u32(sXh), uXl = smem_u32(sXl);

    for (int ch = 0; ch < (SS / NSPLIT) / 64; ch++) {   // 16 chunks of 64 y
        const int yc = ybase + ch * 64;
        // ---- convert X chunk [64 y x 64 c] fp32 -> bf16 hi/lo ----
        for (int t = tid; t < 1024; t += 192) {
            int row = t >> 4, c4 = t & 15;
            float4 v = *reinterpret_cast<const float4*>(xb + (size_t)(yc + row) * HH + c4 * 4);
            uint2 h = make_uint2(pk2(v.x, v.y), pk2(v.z, v.w));
            uint2 lo = make_uint2(pk2(rz(v.x), rz(v.y)), pk2(rz(v.z), rz(v.w)));
            *reinterpret_cast<uint2*>(&sXh[row * CXP + c4 * 4]) = h;
            *reinterpret_cast<uint2*>(&sXl[row * CXP + c4 * 4]) = lo;
        }
        // ---- copy att chunk [48 r x 64 y] bf16 hi/lo ----
        for (int t = tid; t < 384; t += 192) {
            int row = t >> 3, q = t & 7;
            uint4 vh = *reinterpret_cast<const uint4*>(ah + (size_t)row * SS + yc + q * 8);
            uint4 vl = *reinterpret_cast<const uint4*>(al + (size_t)row * SS + yc + q * 8);
            *reinterpret_cast<uint4*>(&sAh[row * CXP + q * 8]) = vh;
            *reinterpret_cast<uint4*>(&sAl[row * CXP + q * 8]) = vl;
        }
        __syncthreads();
        // ---- MMA: 4 k-steps of 16 y ----
        #pragma unroll
        for (int ks = 0; ks < 4; ks++) {
            const int k0 = ks * 16;
            uint32_t arow = mt * 16 + (l & 15);
            uint32_t acol = k0 + ((l >> 4) << 3);
            uint32_t aoff = (arow * CXP + acol) * 2;
            uint32_t fa_h[4], fa_l[4];
            ldsm4(fa_h, uAh + aoff);
            ldsm4(fa_l, uAl + aoff);
            #pragma unroll
            for (int ntp = 0; ntp < 2; ntp++) {
                uint32_t brow = k0 + (l & 15);
                uint32_t bcol = cbase + ntp * 16 + ((l >> 4) << 3);
                uint32_t boff = (brow * CXP + bcol) * 2;
                uint32_t fb_h[4], fb_l[4];
                ldsm4t(fb_h, uXh + boff);
                ldsm4t(fb_l, uXl + boff);
                mma_bf16(acc[ntp * 2],     fa_h, fb_h[0], fb_h[1]);
                mma_bf16(acc[ntp * 2],     fa_h, fb_l[0], fb_l[1]);
                mma_bf16(acc[ntp * 2],     fa_l, fb_h[0], fb_h[1]);
                mma_bf16(acc[ntp * 2 + 1], fa_h, fb_h[2], fb_h[3]);
                mma_bf16(acc[ntp * 2 + 1], fa_h, fb_l[2], fb_l[3]);
                mma_bf16(acc[ntp * 2 + 1], fa_l, fb_h[2], fb_h[3]);
            }
        }
        __syncthreads();
    }

    // ---- epilogue: float2 stores (c pairs contiguous) ----
    float* ob = g_part + (size_t)((b * NSPLIT + sp) * RR) * HH + c0;
    int r0 = mt * 16 + (l >> 2);
    #pragma unroll
    for (int nt = 0; nt < 4; nt++) {
        int c = cbase + nt * 8 + (l & 3) * 2;
        *reinterpret_cast<float2*>(ob + (size_t)r0 * HH + c)       = make_float2(acc[nt][0], acc[nt][1]);
        *reinterpret_cast<float2*>(ob + (size_t)(r0 + 8) * HH + c) = make_float2(acc[nt][2], acc[nt][3]);
    }
}

// =================== Kernel 5: reduce split-K ===================
__global__ void __launch_bounds__(256) k_reduce() {
    int o = blockIdx.x * 256 + threadIdx.x;
    int b = o / (RR * HH);
    int rc = o - b * (RR * HH);
    const float* p = g_part + (size_t)b * NSPLIT * RR * HH + rc;
    float a = 0.f;
    #pragma unroll
    for (int s = 0; s < NSPLIT; s++) a += p[(size_t)s * RR * HH];
    g_ctx[o] = a;
}

// =================== Kernel 6: epilogue ===================
__global__ void __launch_bounds__(256) k_out(const float* __restrict__ wkv,
                                             const float* __restrict__ wout,
                                             const float* __restrict__ bout,
                                             float* __restrict__ out) {
    int b = blockIdx.x >> 2, t = blockIdx.x & 3;
    __shared__ float sc_[NH][HH];
    __shared__ float so[HH];
    for (int idx = threadIdx.x; idx < NH * HH / 4; idx += 256) {
        int h = idx / (HH / 4), c4 = idx % (HH / 4);
        reinterpret_cast<float4*>(&sc_[h][0])[c4] =
            reinterpret_cast<const float4*>(g_ctx + (size_t)((b * RR) + h * NBN + t) * HH)[c4];
    }
    __syncthreads();
    for (int jj = threadIdx.x; jj < HH; jj += 256) {
        int h = jj >> 6;
        const float4* w = reinterpret_cast<const float4*>(wkv + (size_t)(HH + jj) * HH);
        const float4* cr = reinterpret_cast<const float4*>(&sc_[h][0]);
        float a = 0.f;
        #pragma unroll 4
        for (int c4 = 0; c4 < HH / 4; c4++) {
            float4 wv = w[c4], cv = cr[c4];
            a += wv.x * cv.x + wv.y * cv.y + wv.z * cv.z + wv.w * cv.w;
        }
        so[jj] = a;
    }
    __syncthreads();
    for (int jj = threadIdx.x; jj < HH; jj += 256) {
        const float4* w = reinterpret_cast<const float4*>(wout + (size_t)jj * HH);
        const float4* s4 = reinterpret_cast<const float4*>(so);
        float a = bout[jj];
        #pragma unroll 4
        for (int c4 = 0; c4 < HH / 4; c4++) {
            float4 wv = w[c4], sv = s4[c4];
            a += wv.x * sv.x + wv.y * sv.y + wv.z * sv.z + wv.w * sv.w;
        }
        out[(size_t)(b * NBN + t) * HH + jj] = a;
    }
}

// ---------------------------------------------------------------------------
extern "C" void kernel_launch(void* const* d_in, const int* in_sizes, int n_in,
                              void* d_out, int out_size) {
    const float* x    = (const float*)d_in[0];
    const float* wkv  = (const float*)d_in[1];
    const float* wq   = (const float*)d_in[2];
    const float* wout = (const float*)d_in[3];
    const float* bout = (const float*)d_in[4];
    float* out = (float*)d_out;

    k_qproj<<<BB * NBN, 256>>>(x, wq);
    k_qw<<<BB * RR, 256>>>(wkv);
    k_scores_mma<<<dim3(SS / 128, BB), 256>>>(x);
    k_softmax<<<BB * RR, 256>>>();
    k_ctx_mma<<<dim3(HH / 64, NSPLIT, BB), 192>>>(x);
    k_reduce<<<(BB * RR * HH) / 256, 256>>>();
    k_out<<<BB * NBN, 256>>>(wkv, wout, bout, out);
}

// round 5
// speedup vs baseline: 1.6419x; 1.2754x over previous
#include <cuda_runtime.h>
#include <cuda_bf16.h>
#include <cstdint>
#include <math.h>

#define BB 8
#define SS 8192
#define HH 768
#define NH 12
#define HD 64
#define NBN 4
#define RR 48
#define SCALEF 0.125f
#define NSPLIT 8

// ---------------- global scratch ----------------
__device__ __nv_bfloat16 g_qwh[BB*RR*HH];
__device__ __nv_bfloat16 g_qwl[BB*RR*HH];
__device__ float g_sc[(size_t)BB*RR*SS];
__device__ __nv_bfloat16 g_ath[(size_t)BB*RR*SS];
__device__ __nv_bfloat16 g_atl[(size_t)BB*RR*SS];
__device__ float g_part[(size_t)BB*NSPLIT*RR*HH];
__device__ float g_ctx[BB*RR*HH];

// ---------------- helpers ----------------
__device__ __forceinline__ uint32_t smem_u32(const void* p) {
    uint32_t a;
    asm("{ .reg .u64 t; cvta.to.shared.u64 t, %1; cvt.u32.u64 %0, t; }" : "=r"(a) : "l"(p));
    return a;
}
__device__ __forceinline__ void ldsm4(uint32_t* r, uint32_t a) {
    asm volatile("ldmatrix.sync.aligned.m8n8.x4.shared.b16 {%0,%1,%2,%3}, [%4];"
        : "=r"(r[0]), "=r"(r[1]), "=r"(r[2]), "=r"(r[3]) : "r"(a));
}
__device__ __forceinline__ void ldsm4t(uint32_t* r, uint32_t a) {
    asm volatile("ldmatrix.sync.aligned.m8n8.x4.trans.shared.b16 {%0,%1,%2,%3}, [%4];"
        : "=r"(r[0]), "=r"(r[1]), "=r"(r[2]), "=r"(r[3]) : "r"(a));
}
__device__ __forceinline__ void mma_bf16(float* c, const uint32_t* a, uint32_t b0, uint32_t b1) {
    asm volatile("mma.sync.aligned.m16n8k16.row.col.f32.bf16.bf16.f32 "
        "{%0,%1,%2,%3}, {%4,%5,%6,%7}, {%8,%9}, {%0,%1,%2,%3};"
        : "+f"(c[0]), "+f"(c[1]), "+f"(c[2]), "+f"(c[3])
        : "r"(a[0]), "r"(a[1]), "r"(a[2]), "r"(a[3]), "r"(b0), "r"(b1));
}
__device__ __forceinline__ uint32_t pk2(float a, float b) {
    __nv_bfloat162 t = __floats2bfloat162_rn(a, b);
    return *reinterpret_cast<uint32_t*>(&t);
}
__device__ __forceinline__ float rz(float v) {
    return v - __bfloat162float(__float2bfloat16_rn(v));
}

// ========== Kernel 1 (fused): qw[b,r,:] = SCALE*( (x[b,t]·Wq_head) @ W_k_head ) ==========
__global__ void __launch_bounds__(256) k_qw(const float* __restrict__ x,
                                            const float* __restrict__ wq,
                                            const float* __restrict__ wkv) {
    int b = blockIdx.x / RR, r = blockIdx.x % RR;
    int h = r >> 2, t = r & 3;
    __shared__ float sx[HH];
    __shared__ float sq[HD];
    const float* xr = x + ((size_t)b * SS + t) * HH;
    for (int c = threadIdx.x; c < HH; c += 256) sx[c] = xr[c];
    __syncthreads();
    // stage 1: q_d = x_row · wq[h*64+d, :]   (4 lanes per d)
    {
        int d = threadIdx.x >> 2, s = threadIdx.x & 3;
        const float4* wr = reinterpret_cast<const float4*>(wq + (size_t)(h * HD + d) * HH);
        const float4* s4 = reinterpret_cast<const float4*>(sx);
        float a = 0.f;
        #pragma unroll 4
        for (int kk = 0; kk < 48; kk++) {
            int c4 = s + kk * 4;
            float4 wv = wr[c4], sv = s4[c4];
            a += wv.x * sv.x + wv.y * sv.y + wv.z * sv.z + wv.w * sv.w;
        }
        a += __shfl_xor_sync(0xffffffffu, a, 1);
        a += __shfl_xor_sync(0xffffffffu, a, 2);
        if (s == 0) sq[d] = a;
    }
    __syncthreads();
    // stage 2: qw[c] = SCALE * sum_d sq[d] * wkv[h*64+d, c], split bf16
    for (int c = threadIdx.x; c < HH; c += 256) {
        float a = 0.f;
        #pragma unroll 8
        for (int d = 0; d < HD; d++)
            a += sq[d] * wkv[(size_t)(h * HD + d) * HH + c];
        a *= SCALEF;
        size_t idx = (size_t)(b * RR + r) * HH + c;
        __nv_bfloat16 hi = __float2bfloat16_rn(a);
        g_qwh[idx] = hi;
        g_qwl[idx] = __float2bfloat16_rn(a - __bfloat162float(hi));
    }
}

// =================== Kernel 2: scores via mma.sync, prefetch pipelined ===================
#define SXP 40
__global__ void __launch_bounds__(256) k_scores_mma(const float* __restrict__ x) {
    __shared__ __align__(16) char sbuf[28160];
    __nv_bfloat16* sXh = reinterpret_cast<__nv_bfloat16*>(sbuf);            // 128*40*2 = 10240
    __nv_bfloat16* sXl = reinterpret_cast<__nv_bfloat16*>(sbuf + 10240);    // 10240
    __nv_bfloat16* sQh = reinterpret_cast<__nv_bfloat16*>(sbuf + 20480);    // 48*40*2 = 3840
    __nv_bfloat16* sQl = reinterpret_cast<__nv_bfloat16*>(sbuf + 24320);    // 3840

    const int tid = threadIdx.x, w = tid >> 5, l = tid & 31;
    const int b = blockIdx.y;
    const int y0 = blockIdx.x * 128;

    const float* xb = x + ((size_t)b * SS + y0) * HH;
    const __nv_bfloat16* qh = g_qwh + (size_t)b * RR * HH;
    const __nv_bfloat16* ql = g_qwl + (size_t)b * RR * HH;

    float acc[6][4];
    #pragma unroll
    for (int n = 0; n < 6; n++)
        #pragma unroll
        for (int k = 0; k < 4; k++) acc[n][k] = 0.f;

    const uint32_t uXh = smem_u32(sXh), uXl = smem_u32(sXl);
    const uint32_t uQh = smem_u32(sQh), uQl = smem_u32(sQl);

    float4 px[4];
    uint4 pqh, pql;
    const int xrow0 = tid >> 3, xc4 = tid & 7;       // +32 rows per it
    const int qrow = tid >> 2, qq = tid & 3;         // tid<192

    auto LDG = [&](int c0) {
        #pragma unroll
        for (int it = 0; it < 4; it++)
            px[it] = *reinterpret_cast<const float4*>(
                xb + (size_t)(xrow0 + it * 32) * HH + c0 + xc4 * 4);
        if (tid < 192) {
            pqh = *reinterpret_cast<const uint4*>(qh + (size_t)qrow * HH + c0 + qq * 8);
            pql = *reinterpret_cast<const uint4*>(ql + (size_t)qrow * HH + c0 + qq * 8);
        }
    };
    auto STS = [&]() {
        #pragma unroll
        for (int it = 0; it < 4; it++) {
            int row = xrow0 + it * 32;
            float4 v = px[it];
            *reinterpret_cast<uint2*>(&sXh[row * SXP + xc4 * 4]) =
                make_uint2(pk2(v.x, v.y), pk2(v.z, v.w));
            *reinterpret_cast<uint2*>(&sXl[row * SXP + xc4 * 4]) =
                make_uint2(pk2(rz(v.x), rz(v.y)), pk2(rz(v.z), rz(v.w)));
        }
        if (tid < 192) {
            *reinterpret_cast<uint4*>(&sQh[qrow * SXP + qq * 8]) = pqh;
            *reinterpret_cast<uint4*>(&sQl[qrow * SXP + qq * 8]) = pql;
        }
    };
    auto COMP = [&]() {
        #pragma unroll
        for (int ks = 0; ks < 2; ks++) {
            const int k0 = ks * 16;
            uint32_t aoff = ((w * 16 + (l & 15)) * SXP + k0 + ((l >> 4) << 3)) * 2;
            uint32_t ah[4], al[4];
            ldsm4(ah, uXh + aoff);
            ldsm4(al, uXl + aoff);
            #pragma unroll
            for (int ntp = 0; ntp < 3; ntp++) {
                uint32_t boff = ((ntp * 16 + ((l >> 4) << 3) + (l & 7)) * SXP + k0 + (l & 8)) * 2;
                uint32_t bh[4], bl[4];
                ldsm4(bh, uQh + boff);
                ldsm4(bl, uQl + boff);
                mma_bf16(acc[ntp * 2],     ah, bh[0], bh[1]);
                mma_bf16(acc[ntp * 2],     ah, bl[0], bl[1]);
                mma_bf16(acc[ntp * 2],     al, bh[0], bh[1]);
                mma_bf16(acc[ntp * 2 + 1], ah, bh[2], bh[3]);
                mma_bf16(acc[ntp * 2 + 1], ah, bl[2], bl[3]);
                mma_bf16(acc[ntp * 2 + 1], al, bh[2], bh[3]);
            }
        }
    };

    LDG(0);
    STS();
    __syncthreads();
    for (int ch = 1; ch < 24; ch++) {
        LDG(ch * 32);         // prefetch next chunk (latency overlaps COMP)
        COMP();
        __syncthreads();
        STS();
        __syncthreads();
    }
    COMP();
    __syncthreads();

    // ---- staged coalesced epilogue ----
    float* stage = reinterpret_cast<float*>(sbuf);   // stride 136: 48*136*4 = 26112 <= 28160
    {
        int yl = w * 16 + (l >> 2);
        #pragma unroll
        for (int nt = 0; nt < 6; nt++) {
            int r = nt * 8 + (l & 3) * 2;
            stage[r * 136 + yl]           = acc[nt][0];
            stage[(r + 1) * 136 + yl]     = acc[nt][1];
            stage[r * 136 + yl + 8]       = acc[nt][2];
            stage[(r + 1) * 136 + yl + 8] = acc[nt][3];
        }
    }
    __syncthreads();
    float* ob = g_sc + (size_t)b * RR * SS;
    #pragma unroll
    for (int i = tid; i < 48 * 32; i += 256) {
        int r = i >> 5, c4 = i & 31;
        float4 v = *reinterpret_cast<float4*>(&stage[r * 136 + c4 * 4]);
        *reinterpret_cast<float4*>(ob + (size_t)r * SS + y0 + c4 * 4) = v;
    }
}

// =================== Kernel 3: softmax -> bf16 hi/lo ===================
__global__ void __launch_bounds__(256) k_softmax() {
    const int row = blockIdx.x;
    const float* p = g_sc + (size_t)row * SS;
    __nv_bfloat16* oh = g_ath + (size_t)row * SS;
    __nv_bfloat16* ol = g_atl + (size_t)row * SS;
    __shared__ float sv[SS];
    __shared__ float red[8];

    float mx = -1e30f;
    for (int t = threadIdx.x; t < SS / 4; t += 256) {
        float4 v = reinterpret_cast<const float4*>(p)[t];
        reinterpret_cast<float4*>(sv)[t] = v;
        mx = fmaxf(mx, fmaxf(fmaxf(v.x, v.y), fmaxf(v.z, v.w)));
    }
    #pragma unroll
    for (int o = 16; o; o >>= 1) mx = fmaxf(mx, __shfl_xor_sync(0xffffffffu, mx, o));
    if ((threadIdx.x & 31) == 0) red[threadIdx.x >> 5] = mx;
    __syncthreads();
    float m = red[0];
    #pragma unroll
    for (int k = 1; k < 8; k++) m = fmaxf(m, red[k]);
    __syncthreads();

    float sum = 0.f;
    for (int t = threadIdx.x; t < SS / 4; t += 256) {
        float4 v = reinterpret_cast<float4*>(sv)[t];
        v.x = expf(v.x - m); v.y = expf(v.y - m);
        v.z = expf(v.z - m); v.w = expf(v.w - m);
        reinterpret_cast<float4*>(sv)[t] = v;
        sum += v.x + v.y + v.z + v.w;
    }
    #pragma unroll
    for (int o = 16; o; o >>= 1) sum += __shfl_xor_sync(0xffffffffu, sum, o);
    if ((threadIdx.x & 31) == 0) red[threadIdx.x >> 5] = sum;
    __syncthreads();
    float tot = 0.f;
    #pragma unroll
    for (int k = 0; k < 8; k++) tot += red[k];
    float inv = 1.0f / tot;

    for (int t = threadIdx.x; t < SS / 4; t += 256) {
        float4 v = reinterpret_cast<float4*>(sv)[t];
        v.x *= inv; v.y *= inv; v.z *= inv; v.w *= inv;
        reinterpret_cast<uint2*>(oh)[t] = make_uint2(pk2(v.x, v.y), pk2(v.z, v.w));
        reinterpret_cast<uint2*>(ol)[t] = make_uint2(pk2(rz(v.x), rz(v.y)), pk2(rz(v.z), rz(v.w)));
    }
}

// =================== Kernel 4: ctx via mma.sync, prefetch pipelined ===================
#define CXP 72
__global__ void __launch_bounds__(192) k_ctx_mma(const float* __restrict__ x) {
    __shared__ __nv_bfloat16 sAh[48 * CXP];
    __shared__ __nv_bfloat16 sAl[48 * CXP];
    __shared__ __nv_bfloat16 sXh[64 * CXP];
    __shared__ __nv_bfloat16 sXl[64 * CXP];

    const int tid = threadIdx.x, w = tid >> 5, l = tid & 31;
    const int ct = blockIdx.x;
    const int sp = blockIdx.y;
    const int b  = blockIdx.z;
    const int c0 = ct * 64;
    const int ybase = sp * (SS / NSPLIT);

    const float* xb = x + (size_t)b * SS * HH + c0;
    const __nv_bfloat16* ah = g_ath + (size_t)b * RR * SS;
    const __nv_bfloat16* al = g_atl + (size_t)b * RR * SS;

    const int mt = w >> 1;
    const int cbase = (w & 1) * 32;

    float acc[4][4];
    #pragma unroll
    for (int n = 0; n < 4; n++)
        #pragma unroll
        for (int k = 0; k < 4; k++) acc[n][k] = 0.f;

    const uint32_t uAh = smem_u32(sAh), uAl = smem_u32(sAl);
    const uint32_t uXh = smem_u32(sXh), uXl = smem_u32(sXl);

    float4 px[6];
    uint4 pah[2], pal[2];

    auto LDG = [&](int yc) {
        #pragma unroll
        for (int it = 0; it < 6; it++) {
            int t = tid + 192 * it;
            if (t < 1024) {
                int row = t >> 4, c4 = t & 15;
                px[it] = *reinterpret_cast<const float4*>(
                    xb + (size_t)(yc + row) * HH + c4 * 4);
            }
        }
        #pragma unroll
        for (int it = 0; it < 2; it++) {
            int t = tid + 192 * it;
            if (t < 384) {
                int row = t >> 3, q = t & 7;
                pah[it] = *reinterpret_cast<const uint4*>(ah + (size_t)row * SS + yc + q * 8);
                pal[it] = *reinterpret_cast<const uint4*>(al + (size_t)row * SS + yc + q * 8);
            }
        }
    };
    auto STS = [&]() {
        #pragma unroll
        for (int it = 0; it < 6; it++) {
            int t = tid + 192 * it;
            if (t < 1024) {
                int row = t >> 4, c4 = t & 15;
                float4 v = px[it];
                *reinterpret_cast<uint2*>(&sXh[row * CXP + c4 * 4]) =
                    make_uint2(pk2(v.x, v.y), pk2(v.z, v.w));
                *reinterpret_cast<uint2*>(&sXl[row * CXP + c4 * 4]) =
                    make_uint2(pk2(rz(v.x), rz(v.y)), pk2(rz(v.z), rz(v.w)));
            }
        }
        #pragma unroll
        for (int it = 0; it < 2; it++) {
            int t = tid + 192 * it;
            if (t < 384) {
                int row = t >> 3, q = t & 7;
                *reinterpret_cast<uint4*>(&sAh[row * CXP + q * 8]) = pah[it];
                *reinterpret_cast<uint4*>(&sAl[row * CXP + q * 8]) = pal[it];
            }
        }
    };
    auto COMP = [&]() {
        #pragma unroll
        for (int ks = 0; ks < 4; ks++) {
            const int k0 = ks * 16;
            uint32_t aoff = ((mt * 16 + (l & 15)) * CXP + k0 + ((l >> 4) << 3)) * 2;
            uint32_t fa_h[4], fa_l[4];
            ldsm4(fa_h, uAh + aoff);
            ldsm4(fa_l, uAl + aoff);
            #pragma unroll
            for (int ntp = 0; ntp < 2; ntp++) {
                uint32_t boff = ((k0 + (l & 15)) * CXP + cbase + ntp * 16 + ((l >> 4) << 3)) * 2;
                uint32_t fb_h[4], fb_l[4];
                ldsm4t(fb_h, uXh + boff);
                ldsm4t(fb_l, uXl + boff);
                mma_bf16(acc[ntp * 2],     fa_h, fb_h[0], fb_h[1]);
                mma_bf16(acc[ntp * 2],     fa_h, fb_l[0], fb_l[1]);
                mma_bf16(acc[ntp * 2],     fa_l, fb_h[0], fb_h[1]);
                mma_bf16(acc[ntp * 2 + 1], fa_h, fb_h[2], fb_h[3]);
                mma_bf16(acc[ntp * 2 + 1], fa_h, fb_l[2], fb_l[3]);
                mma_bf16(acc[ntp * 2 + 1], fa_l, fb_h[2], fb_h[3]);
            }
        }
    };

    LDG(ybase);
    STS();
    __syncthreads();
    for (int ch = 1; ch < (SS / NSPLIT) / 64; ch++) {
        LDG(ybase + ch * 64);   // prefetch (latency overlaps COMP)
        COMP();
        __syncthreads();
        STS();
        __syncthreads();
    }
    COMP();

    float* ob = g_part + (size_t)((b * NSPLIT + sp) * RR) * HH + c0;
    int r0 = mt * 16 + (l >> 2);
    #pragma unroll
    for (int nt = 0; nt < 4; nt++) {
        int c = cbase + nt * 8 + (l & 3) * 2;
        *reinterpret_cast<float2*>(ob + (size_t)r0 * HH + c)       = make_float2(acc[nt][0], acc[nt][1]);
        *reinterpret_cast<float2*>(ob + (size_t)(r0 + 8) * HH + c) = make_float2(acc[nt][2], acc[nt][3]);
    }
}

// =================== Kernel 5: reduce split-K ===================
__global__ void __launch_bounds__(256) k_reduce() {
    int o = blockIdx.x * 256 + threadIdx.x;
    int b = o / (RR * HH);
    int rc = o - b * (RR * HH);
    const float* p = g_part + (size_t)b * NSPLIT * RR * HH + rc;
    float a = 0.f;
    #pragma unroll
    for (int s = 0; s < NSPLIT; s++) a += p[(size_t)s * RR * HH];
    g_ctx[o] = a;
}

// =================== Kernel 6: epilogue ===================
__global__ void __launch_bounds__(256) k_out(const float* __restrict__ wkv,
                                             const float* __restrict__ wout,
                                             const float* __restrict__ bout,
                                             float* __restrict__ out) {
    int b = blockIdx.x >> 2, t = blockIdx.x & 3;
    __shared__ float sc_[NH][HH];
    __shared__ float so[HH];
    for (int idx = threadIdx.x; idx < NH * HH / 4; idx += 256) {
        int h = idx / (HH / 4), c4 = idx % (HH / 4);
        reinterpret_cast<float4*>(&sc_[h][0])[c4] =
            reinterpret_cast<const float4*>(g_ctx + (size_t)((b * RR) + h * NBN + t) * HH)[c4];
    }
    __syncthreads();
    for (int jj = threadIdx.x; jj < HH; jj += 256) {
        int h = jj >> 6;
        const float4* w = reinterpret_cast<const float4*>(wkv + (size_t)(HH + jj) * HH);
        const float4* cr = reinterpret_cast<const float4*>(&sc_[h][0]);
        float a = 0.f;
        #pragma unroll 4
        for (int c4 = 0; c4 < HH / 4; c4++) {
            float4 wv = w[c4], cv = cr[c4];
            a += wv.x * cv.x + wv.y * cv.y + wv.z * cv.z + wv.w * cv.w;
        }
        so[jj] = a;
    }
    __syncthreads();
    for (int jj = threadIdx.x; jj < HH; jj += 256) {
        const float4* w = reinterpret_cast<const float4*>(wout + (size_t)jj * HH);
        const float4* s4 = reinterpret_cast<const float4*>(so);
        float a = bout[jj];
        #pragma unroll 4
        for (int c4 = 0; c4 < HH / 4; c4++) {
            float4 wv = w[c4], sv = s4[c4];
            a += wv.x * sv.x + wv.y * sv.y + wv.z * sv.z + wv.w * sv.w;
        }
        out[(size_t)(b * NBN + t) * HH + jj] = a;
    }
}

// ---------------------------------------------------------------------------
extern "C" void kernel_launch(void* const* d_in, const int* in_sizes, int n_in,
                              void* d_out, int out_size) {
    const float* x    = (const float*)d_in[0];
    const float* wkv  = (const float*)d_in[1];
    const float* wq   = (const float*)d_in[2];
    const float* wout = (const float*)d_in[3];
    const float* bout = (const float*)d_in[4];
    float* out = (float*)d_out;

    k_qw<<<BB * RR, 256>>>(x, wq, wkv);                     // launch 1
    k_scores_mma<<<dim3(SS / 128, BB), 256>>>(x);           // launch 2
    k_softmax<<<BB * RR, 256>>>();                          // launch 3
    k_ctx_mma<<<dim3(HH / 64, NSPLIT, BB), 192>>>(x);       // launch 4 (ncu capture slot)
    k_reduce<<<(BB * RR * HH) / 256, 256>>>();              // launch 5
    k_out<<<BB * NBN, 256>>>(wkv, wout, bout, out);         // launch 6
}